// round 1
// baseline (speedup 1.0000x reference)
#include <cuda_runtime.h>

// realignment_layer: outputs = [batch_T_pred (32*4*4), pcd_new (32*262144*3)] f32
//
// inv(delta_T) for delta_T = [[R,t],[0,1]] with orthonormal R is [[R^T, -R^T t],[0,1]].
// Kernel 1 computes batch_T_pred = inv_T @ T_mis (tiny).
// Kernel 2 streams the point cloud: p' = R^T p - R^T t, vectorized as float4.

#define BQ(b) (dq + (b) * 4)
#define BT(b) (dt + (b) * 3)

// Compute the 3x3 inverse rotation (R^T) and inverse translation from quaternion+t.
__device__ __forceinline__ void inv_rt(const float* __restrict__ q4,
                                       const float* __restrict__ t3,
                                       float m[3][3], float it[3]) {
    float w = q4[0], x = q4[1], y = q4[2], z = q4[3];
    float inv_n = rsqrtf(w * w + x * x + y * y + z * z);
    w *= inv_n; x *= inv_n; y *= inv_n; z *= inv_n;

    float xx = x * x, yy = y * y, zz = z * z;
    float xy = x * y, xz = x * z, yz = y * z;
    float wx = w * x, wy = w * y, wz = w * z;

    // R (row-major)
    float r00 = 1.0f - 2.0f * (yy + zz);
    float r01 = 2.0f * (xy - wz);
    float r02 = 2.0f * (xz + wy);
    float r10 = 2.0f * (xy + wz);
    float r11 = 1.0f - 2.0f * (xx + zz);
    float r12 = 2.0f * (yz - wx);
    float r20 = 2.0f * (xz - wy);
    float r21 = 2.0f * (yz + wx);
    float r22 = 1.0f - 2.0f * (xx + yy);

    // m = R^T
    m[0][0] = r00; m[0][1] = r10; m[0][2] = r20;
    m[1][0] = r01; m[1][1] = r11; m[1][2] = r21;
    m[2][0] = r02; m[2][1] = r12; m[2][2] = r22;

    float t0 = t3[0], t1 = t3[1], t2 = t3[2];
    it[0] = -(m[0][0] * t0 + m[0][1] * t1 + m[0][2] * t2);
    it[1] = -(m[1][0] * t0 + m[1][1] * t1 + m[1][2] * t2);
    it[2] = -(m[2][0] * t0 + m[2][1] * t1 + m[2][2] * t2);
}

// One thread per batch: batch_T_pred[b] = inv_T[b] @ T_mis[b]
__global__ void tpred_kernel(const float* __restrict__ Tm,
                             const float* __restrict__ dq,
                             const float* __restrict__ dt,
                             float* __restrict__ out, int B) {
    int b = blockIdx.x * blockDim.x + threadIdx.x;
    if (b >= B) return;

    float m[3][3], it[3];
    inv_rt(BQ(b), BT(b), m, it);

    const float* T = Tm + b * 16;
    float* o = out + b * 16;

    // rows 0..2: sum_j m[i][j]*T[j][k] + it[i]*T[3][k]
    #pragma unroll
    for (int i = 0; i < 3; i++) {
        #pragma unroll
        for (int k = 0; k < 4; k++) {
            float acc = it[i] * T[12 + k];
            acc += m[i][0] * T[0 + k];
            acc += m[i][1] * T[4 + k];
            acc += m[i][2] * T[8 + k];
            o[i * 4 + k] = acc;
        }
    }
    // row 3 of inv_T is (0,0,0,1) -> copy T row 3
    #pragma unroll
    for (int k = 0; k < 4; k++) o[12 + k] = T[12 + k];
}

// Streaming point transform. Each thread: 3 float4 in -> 4 points -> 3 float4 out.
// f4_per_batch = N*3/4 (divisible by 3 for N=262144).
__global__ void __launch_bounds__(256) pts_kernel(
    const float4* __restrict__ pcd,
    const float* __restrict__ dq,
    const float* __restrict__ dt,
    float4* __restrict__ out,
    int f4_per_batch) {
    int b = blockIdx.y;
    int tid = blockIdx.x * blockDim.x + threadIdx.x;
    long i0 = (long)tid * 3;
    if (i0 + 3 > f4_per_batch) return;

    long base = (long)b * f4_per_batch + i0;

    // Batch-broadcast transform (L2-resident; ~40 FLOPs hidden under LDG latency)
    float m[3][3], it[3];
    inv_rt(BQ(b), BT(b), m, it);

    float4 va = pcd[base + 0];
    float4 vb = pcd[base + 1];
    float4 vc = pcd[base + 2];

    // unpack 4 points
    float px[4] = {va.x, va.w, vb.z, vc.y};
    float py[4] = {va.y, vb.x, vb.w, vc.z};
    float pz[4] = {va.z, vb.y, vc.x, vc.w};

    float ox[4], oy[4], oz[4];
    #pragma unroll
    for (int p = 0; p < 4; p++) {
        ox[p] = fmaf(m[0][0], px[p], fmaf(m[0][1], py[p], fmaf(m[0][2], pz[p], it[0])));
        oy[p] = fmaf(m[1][0], px[p], fmaf(m[1][1], py[p], fmaf(m[1][2], pz[p], it[1])));
        oz[p] = fmaf(m[2][0], px[p], fmaf(m[2][1], py[p], fmaf(m[2][2], pz[p], it[2])));
    }

    float4 wa = make_float4(ox[0], oy[0], oz[0], ox[1]);
    float4 wb = make_float4(oy[1], oz[1], ox[2], oy[2]);
    float4 wc = make_float4(oz[2], ox[3], oy[3], oz[3]);

    out[base + 0] = wa;
    out[base + 1] = wb;
    out[base + 2] = wc;
}

extern "C" void kernel_launch(void* const* d_in, const int* in_sizes, int n_in,
                              void* d_out, int out_size) {
    const float* pcd = (const float*)d_in[0];   // (B, N, 3)
    const float* Tm  = (const float*)d_in[1];   // (B, 4, 4)
    const float* dq  = (const float*)d_in[2];   // (B, 4)
    const float* dt  = (const float*)d_in[3];   // (B, 3)
    float* out = (float*)d_out;

    int B = in_sizes[1] / 16;                   // 32
    long n_pcd = in_sizes[0];                   // B*N*3
    int floats_per_batch = (int)(n_pcd / B);    // N*3 = 786432
    int f4_per_batch = floats_per_batch / 4;    // 196608 (divisible by 3)

    float* out_T = out;                          // first B*16 floats
    float4* out_pcd = (float4*)(out + (long)B * 16);  // 2048-byte offset, 16B aligned

    // Tiny kernel for batch_T_pred
    tpred_kernel<<<1, 32>>>(Tm, dq, dt, out_T, B);

    // Streaming kernel: threads_per_batch = f4_per_batch/3
    int threads_per_batch = f4_per_batch / 3;    // 65536
    dim3 block(256);
    dim3 grid((threads_per_batch + 255) / 256, B);
    pts_kernel<<<grid, block>>>((const float4*)pcd, dq, dt, out_pcd, f4_per_batch);
}

// round 8
// speedup vs baseline: 1.0944x; 1.0944x over previous
#include <cuda_runtime.h>

// realignment_layer: outputs = [batch_T_pred (32*4*4), pcd_new (32*262144*3)] f32
//
// inv(delta_T) for delta_T = [[R,t],[0,1]] with orthonormal R is [[R^T, -R^T t],[0,1]].
// Single fused kernel: all threads stream the point cloud (p' = R^T p - R^T t,
// 3x float4 per thread); warp 0 of block (0,0) additionally computes
// batch_T_pred = inv_T @ T_mis (one lane per batch, B=32).

__device__ __forceinline__ void inv_rt_ldg(const float* __restrict__ dq,
                                           const float* __restrict__ dt,
                                           int b,
                                           float m[3][3], float it[3]) {
    const float* q4 = dq + b * 4;
    const float* t3 = dt + b * 3;
    float w = __ldg(q4 + 0), x = __ldg(q4 + 1), y = __ldg(q4 + 2), z = __ldg(q4 + 3);
    float inv_n = rsqrtf(w * w + x * x + y * y + z * z);
    w *= inv_n; x *= inv_n; y *= inv_n; z *= inv_n;

    float xx = x * x, yy = y * y, zz = z * z;
    float xy = x * y, xz = x * z, yz = y * z;
    float wx = w * x, wy = w * y, wz = w * z;

    float r00 = 1.0f - 2.0f * (yy + zz);
    float r01 = 2.0f * (xy - wz);
    float r02 = 2.0f * (xz + wy);
    float r10 = 2.0f * (xy + wz);
    float r11 = 1.0f - 2.0f * (xx + zz);
    float r12 = 2.0f * (yz - wx);
    float r20 = 2.0f * (xz - wy);
    float r21 = 2.0f * (yz + wx);
    float r22 = 1.0f - 2.0f * (xx + yy);

    // m = R^T
    m[0][0] = r00; m[0][1] = r10; m[0][2] = r20;
    m[1][0] = r01; m[1][1] = r11; m[1][2] = r21;
    m[2][0] = r02; m[2][1] = r12; m[2][2] = r22;

    float t0 = __ldg(t3 + 0), t1 = __ldg(t3 + 1), t2 = __ldg(t3 + 2);
    it[0] = -(m[0][0] * t0 + m[0][1] * t1 + m[0][2] * t2);
    it[1] = -(m[1][0] * t0 + m[1][1] * t1 + m[1][2] * t2);
    it[2] = -(m[2][0] * t0 + m[2][1] * t1 + m[2][2] * t2);
}

// Fused: point-cloud stream + (block 0, warp 0) batch_T_pred.
__global__ void __launch_bounds__(256) realign_kernel(
    const float4* __restrict__ pcd,
    const float* __restrict__ Tm,
    const float* __restrict__ dq,
    const float* __restrict__ dt,
    float* __restrict__ out_T,
    float4* __restrict__ out_pcd,
    int f4_per_batch, int B) {

    int b = blockIdx.y;
    int tid = blockIdx.x * blockDim.x + threadIdx.x;
    long i0 = (long)tid * 3;

    // Batch-broadcast transform (L2-resident broadcast; hidden under LDG latency)
    float m[3][3], it[3];
    inv_rt_ldg(dq, dt, b, m, it);

    if (i0 + 3 <= (long)f4_per_batch) {
        long base = (long)b * f4_per_batch + i0;

        // Streaming loads: zero reuse, evict-first
        float4 va = __ldcs(&pcd[base + 0]);
        float4 vb = __ldcs(&pcd[base + 1]);
        float4 vc = __ldcs(&pcd[base + 2]);

        // unpack 4 points
        float px[4] = {va.x, va.w, vb.z, vc.y};
        float py[4] = {va.y, vb.x, vb.w, vc.z};
        float pz[4] = {va.z, vb.y, vc.x, vc.w};

        float ox[4], oy[4], oz[4];
        #pragma unroll
        for (int p = 0; p < 4; p++) {
            ox[p] = fmaf(m[0][0], px[p], fmaf(m[0][1], py[p], fmaf(m[0][2], pz[p], it[0])));
            oy[p] = fmaf(m[1][0], px[p], fmaf(m[1][1], py[p], fmaf(m[1][2], pz[p], it[1])));
            oz[p] = fmaf(m[2][0], px[p], fmaf(m[2][1], py[p], fmaf(m[2][2], pz[p], it[2])));
        }

        __stcs(&out_pcd[base + 0], make_float4(ox[0], oy[0], oz[0], ox[1]));
        __stcs(&out_pcd[base + 1], make_float4(oy[1], oz[1], ox[2], oy[2]));
        __stcs(&out_pcd[base + 2], make_float4(oz[2], ox[3], oy[3], oz[3]));
    }

    // Fused batch_T_pred: block (0,0), warp 0, one lane per batch.
    if (blockIdx.x == 0 && blockIdx.y == 0 && threadIdx.x < 32) {
        int bb = threadIdx.x;
        if (bb < B) {
            float mm[3][3], itt[3];
            inv_rt_ldg(dq, dt, bb, mm, itt);

            const float* T = Tm + bb * 16;
            float* o = out_T + bb * 16;

            #pragma unroll
            for (int i = 0; i < 3; i++) {
                #pragma unroll
                for (int k = 0; k < 4; k++) {
                    float acc = itt[i] * __ldg(T + 12 + k);
                    acc = fmaf(mm[i][0], __ldg(T + 0 + k), acc);
                    acc = fmaf(mm[i][1], __ldg(T + 4 + k), acc);
                    acc = fmaf(mm[i][2], __ldg(T + 8 + k), acc);
                    o[i * 4 + k] = acc;
                }
            }
            #pragma unroll
            for (int k = 0; k < 4; k++) o[12 + k] = __ldg(T + 12 + k);
        }
    }
}

extern "C" void kernel_launch(void* const* d_in, const int* in_sizes, int n_in,
                              void* d_out, int out_size) {
    const float* pcd = (const float*)d_in[0];   // (B, N, 3)
    const float* Tm  = (const float*)d_in[1];   // (B, 4, 4)
    const float* dq  = (const float*)d_in[2];   // (B, 4)
    const float* dt  = (const float*)d_in[3];   // (B, 3)
    float* out = (float*)d_out;

    int B = in_sizes[1] / 16;                   // 32
    long n_pcd = in_sizes[0];                   // B*N*3
    int floats_per_batch = (int)(n_pcd / B);    // N*3 = 786432
    int f4_per_batch = floats_per_batch / 4;    // 196608 (divisible by 3)

    float* out_T = out;                                   // first B*16 floats
    float4* out_pcd = (float4*)(out + (long)B * 16);      // 16B aligned

    int threads_per_batch = f4_per_batch / 3;    // 65536
    dim3 block(256);
    dim3 grid((threads_per_batch + 255) / 256, B);
    realign_kernel<<<grid, block>>>((const float4*)pcd, Tm, dq, dt,
                                    out_T, out_pcd, f4_per_batch, B);
}